// round 4
// baseline (speedup 1.0000x reference)
#include <cuda_runtime.h>

// Problem constants
#define Bc 2
#define Tc 2048
#define Cc 2048
#define NHEAD 32
#define NGRP 8
#define HS 64
#define QKVN 3072   // (32 + 2*8) * 64

// Scratch (static device globals: no allocation in kernel_launch)
__device__ float g_qkv[(size_t)Bc * Tc * QKVN];  // [b, t, g, r(0..5), d]  r: q0..q3,k,v
__device__ float g_att[(size_t)Bc * Tc * Cc];    // [b, t, h, d]

// ---------------------------------------------------------------------------
// SGEMM with bias:  C[m][n] = sum_k A[m][k] * W[n][k] + bias[n]
// A: [M,K] row-major, W: [N,K] row-major. BM=BN=128, BK=8, 8x8 microtile.
// Double-buffered smem (explicit ping/pong), one __syncthreads per k-step.
// ---------------------------------------------------------------------------
__device__ __forceinline__ void sg_compute8(
    const float (*As)[128], const float (*Bs)[128],
    int ty, int tx, float acc[8][8])
{
#pragma unroll
    for (int k = 0; k < 8; k++) {
        float ra[8], rb[8];
        *(float4*)&ra[0] = *(const float4*)&As[k][ty * 8];
        *(float4*)&ra[4] = *(const float4*)&As[k][ty * 8 + 4];
        *(float4*)&rb[0] = *(const float4*)&Bs[k][tx * 8];
        *(float4*)&rb[4] = *(const float4*)&Bs[k][tx * 8 + 4];
#pragma unroll
        for (int i = 0; i < 8; i++)
#pragma unroll
            for (int j = 0; j < 8; j++)
                acc[i][j] += ra[i] * rb[j];
    }
}

__global__ __launch_bounds__(256) void sgemm_bias_kernel(
    const float* __restrict__ A, const float* __restrict__ W,
    const float* __restrict__ bias, float* __restrict__ C,
    int M, int N, int K)
{
    __shared__ float As0[8][128], As1[8][128];
    __shared__ float Bs0[8][128], Bs1[8][128];

    const int tid = threadIdx.x;
    const int tx = tid & 15;        // 0..15  (N microtile)
    const int ty = tid >> 4;        // 0..15  (M microtile)
    const int m0 = blockIdx.y * 128;
    const int n0 = blockIdx.x * 128;

    const int lr = tid >> 1;        // 0..127 tile row to load
    const int lc = (tid & 1) * 4;   // k offset 0 or 4

    const float* Aptr = A + (size_t)(m0 + lr) * K + lc;
    const float* Wptr = W + (size_t)(n0 + lr) * K + lc;

    float acc[8][8];
#pragma unroll
    for (int i = 0; i < 8; i++)
#pragma unroll
        for (int j = 0; j < 8; j++) acc[i][j] = 0.f;

    // Prologue: fill buffer 0
    {
        float4 a = *(const float4*)(Aptr);
        float4 b = *(const float4*)(Wptr);
        As0[lc + 0][lr] = a.x; As0[lc + 1][lr] = a.y;
        As0[lc + 2][lr] = a.z; As0[lc + 3][lr] = a.w;
        Bs0[lc + 0][lr] = b.x; Bs0[lc + 1][lr] = b.y;
        Bs0[lc + 2][lr] = b.z; Bs0[lc + 3][lr] = b.w;
    }
    __syncthreads();

    // Main loop: two k-steps per iteration (explicit ping/pong).
    // K is a multiple of 16 for all our shapes (2048).
    int k0 = 8;
    for (; k0 + 8 < K; k0 += 16) {
        // ping: prefetch into buf1, compute buf0
        {
            float4 a = *(const float4*)(Aptr + k0);
            float4 b = *(const float4*)(Wptr + k0);
            sg_compute8(As0, Bs0, ty, tx, acc);
            As1[lc + 0][lr] = a.x; As1[lc + 1][lr] = a.y;
            As1[lc + 2][lr] = a.z; As1[lc + 3][lr] = a.w;
            Bs1[lc + 0][lr] = b.x; Bs1[lc + 1][lr] = b.y;
            Bs1[lc + 2][lr] = b.z; Bs1[lc + 3][lr] = b.w;
            __syncthreads();
        }
        // pong: prefetch into buf0, compute buf1
        {
            float4 a = *(const float4*)(Aptr + k0 + 8);
            float4 b = *(const float4*)(Wptr + k0 + 8);
            sg_compute8(As1, Bs1, ty, tx, acc);
            As0[lc + 0][lr] = a.x; As0[lc + 1][lr] = a.y;
            As0[lc + 2][lr] = a.z; As0[lc + 3][lr] = a.w;
            Bs0[lc + 0][lr] = b.x; Bs0[lc + 1][lr] = b.y;
            Bs0[lc + 2][lr] = b.z; Bs0[lc + 3][lr] = b.w;
            __syncthreads();
        }
    }
    // Tail: one remaining prefetch step (K % 16 == 8 relative to prologue)
    {
        float4 a = *(const float4*)(Aptr + k0);
        float4 b = *(const float4*)(Wptr + k0);
        sg_compute8(As0, Bs0, ty, tx, acc);
        As1[lc + 0][lr] = a.x; As1[lc + 1][lr] = a.y;
        As1[lc + 2][lr] = a.z; As1[lc + 3][lr] = a.w;
        Bs1[lc + 0][lr] = b.x; Bs1[lc + 1][lr] = b.y;
        Bs1[lc + 2][lr] = b.z; Bs1[lc + 3][lr] = b.w;
        __syncthreads();
        sg_compute8(As1, Bs1, ty, tx, acc);
    }

    // Epilogue: bias + vectorized stores (two STG.128 per row)
    float4 bb0 = *(const float4*)(bias + n0 + tx * 8);
    float4 bb1 = *(const float4*)(bias + n0 + tx * 8 + 4);
#pragma unroll
    for (int i = 0; i < 8; i++) {
        float* crow = C + (size_t)(m0 + ty * 8 + i) * N + n0 + tx * 8;
        float4 v0, v1;
        v0.x = acc[i][0] + bb0.x; v0.y = acc[i][1] + bb0.y;
        v0.z = acc[i][2] + bb0.z; v0.w = acc[i][3] + bb0.w;
        v1.x = acc[i][4] + bb1.x; v1.y = acc[i][5] + bb1.y;
        v1.z = acc[i][6] + bb1.z; v1.w = acc[i][7] + bb1.w;
        *(float4*)(crow)     = v0;
        *(float4*)(crow + 4) = v1;
    }
}

// ---------------------------------------------------------------------------
// RoPE in-place on q (r=0..3) and k (r=4) rows of g_qkv.
// cos/sin: [T, 64] with halves duplicated.
// ---------------------------------------------------------------------------
__global__ __launch_bounds__(256) void rope_kernel(const float* __restrict__ cosb,
                                                   const float* __restrict__ sinb)
{
    int idx = blockIdx.x * 256 + threadIdx.x;   // total = B*T*G*5*32
    int d    = idx & 31;
    int idx2 = idx >> 5;
    int r    = idx2 % 5;
    int idx3 = idx2 / 5;          // = b*16384 + t*8 + g
    int g    = idx3 & 7;
    int t    = (idx3 >> 3) & 2047;
    int b    = idx3 >> 14;

    float* base = g_qkv + (size_t)(b * Tc + t) * QKVN + g * 384 + r * 64;
    float c1 = cosb[t * 64 + d],      s1 = sinb[t * 64 + d];
    float c2 = cosb[t * 64 + 32 + d], s2 = sinb[t * 64 + 32 + d];
    float x1 = base[d], x2 = base[d + 32];
    base[d]      = x1 * c1 - x2 * s1;
    base[d + 32] = x2 * c2 + x1 * s2;
}

// ---------------------------------------------------------------------------
// Causal flash attention. One block per (row-tile of 64, head, batch).
// Online softmax, 4x4 register microtiles for QK^T and PV.
// ---------------------------------------------------------------------------
#define PAD 65

__global__ __launch_bounds__(256) void attn_kernel(const float* __restrict__ qkv,
                                                   float* __restrict__ out)
{
    extern __shared__ float sm[];
    float* sQ     = sm;                 // [64][64]
    float* sKV    = sQ + 64 * 64;       // [64][PAD]
    float* sP     = sKV + 64 * PAD;     // [64][PAD]
    float* sM     = sP + 64 * PAD;      // [64]
    float* sL     = sM + 64;            // [64]
    float* sAlpha = sL + 64;            // [64]

    const int tid = threadIdx.x;
    const int i0 = blockIdx.x * 64;     // query row tile base
    const int h  = blockIdx.y;          // head 0..31
    const int b  = blockIdx.z;
    const int g  = h >> 2;              // kv group
    const int qi = h & 3;
    const float scale = 0.125f;         // 1/sqrt(64)

    const float* qbase = qkv + (size_t)b * Tc * QKVN + g * 384 + qi * 64;
    const float* kbase = qkv + (size_t)b * Tc * QKVN + g * 384 + 4 * 64;
    const float* vbase = qkv + (size_t)b * Tc * QKVN + g * 384 + 5 * 64;

    const int llr = tid >> 4;           // 0..15 loader row
    const int llc = (tid & 15) * 4;     // 0..60 loader col

    // Load Q tile (scale folded in)
#pragma unroll
    for (int u = 0; u < 4; u++) {
        int row = llr + u * 16;
        float4 v = *(const float4*)(qbase + (size_t)(i0 + row) * QKVN + llc);
        float* dst = sQ + row * 64 + llc;
        dst[0] = v.x * scale; dst[1] = v.y * scale;
        dst[2] = v.z * scale; dst[3] = v.w * scale;
    }
    if (tid < 64) { sM[tid] = -1e30f; sL[tid] = 0.f; }

    const int tx = tid & 15, ty = tid >> 4;   // GEMM microtile mapping
    const int r4  = tid >> 2;                 // softmax row (0..63)
    const int c16 = (tid & 3) * 16;           // softmax col chunk

    float O[16];
#pragma unroll
    for (int i = 0; i < 16; i++) O[i] = 0.f;

    __syncthreads();

    const int ntiles = (i0 >> 6) + 1;
    for (int jt = 0; jt < ntiles; jt++) {
        const int j0 = jt * 64;

        // Load K tile
#pragma unroll
        for (int u = 0; u < 4; u++) {
            int row = llr + u * 16;
            float4 v = *(const float4*)(kbase + (size_t)(j0 + row) * QKVN + llc);
            float* dst = sKV + row * PAD + llc;
            dst[0] = v.x; dst[1] = v.y; dst[2] = v.z; dst[3] = v.w;
        }
        __syncthreads();

        // GEMM1: S = Qs @ K^T, mask, store to sP
        {
            float s[4][4];
#pragma unroll
            for (int i = 0; i < 4; i++)
#pragma unroll
                for (int j = 0; j < 4; j++) s[i][j] = 0.f;
#pragma unroll 8
            for (int d = 0; d < 64; d++) {
                float qa[4], kb[4];
#pragma unroll
                for (int i = 0; i < 4; i++) qa[i] = sQ[(ty * 4 + i) * 64 + d];
#pragma unroll
                for (int j = 0; j < 4; j++) kb[j] = sKV[(tx * 4 + j) * PAD + d];
#pragma unroll
                for (int i = 0; i < 4; i++)
#pragma unroll
                    for (int j = 0; j < 4; j++) s[i][j] += qa[i] * kb[j];
            }
#pragma unroll
            for (int i = 0; i < 4; i++)
#pragma unroll
                for (int j = 0; j < 4; j++) {
                    int grow = i0 + ty * 4 + i;
                    int gcol = j0 + tx * 4 + j;
                    sP[(ty * 4 + i) * PAD + tx * 4 + j] =
                        (gcol <= grow) ? s[i][j] : -1e30f;
                }
        }
        __syncthreads();

        // Load V tile (overwrites K; safe after sync) + online softmax on sP
#pragma unroll
        for (int u = 0; u < 4; u++) {
            int row = llr + u * 16;
            float4 v = *(const float4*)(vbase + (size_t)(j0 + row) * QKVN + llc);
            float* dst = sKV + row * PAD + llc;
            dst[0] = v.x; dst[1] = v.y; dst[2] = v.z; dst[3] = v.w;
        }
        {
            float p[16];
            float m_tile = -1e30f;
#pragma unroll
            for (int k = 0; k < 16; k++) {
                p[k] = sP[r4 * PAD + c16 + k];
                m_tile = fmaxf(m_tile, p[k]);
            }
            m_tile = fmaxf(m_tile, __shfl_xor_sync(0xffffffffu, m_tile, 1));
            m_tile = fmaxf(m_tile, __shfl_xor_sync(0xffffffffu, m_tile, 2));
            float m_old = sM[r4];
            float m_new = fmaxf(m_old, m_tile);
            float alpha = __expf(m_old - m_new);
            float sum = 0.f;
#pragma unroll
            for (int k = 0; k < 16; k++) {
                p[k] = __expf(p[k] - m_new);
                sum += p[k];
            }
            sum += __shfl_xor_sync(0xffffffffu, sum, 1);
            sum += __shfl_xor_sync(0xffffffffu, sum, 2);
#pragma unroll
            for (int k = 0; k < 16; k++) sP[r4 * PAD + c16 + k] = p[k];
            if ((tid & 3) == 0) {
                sM[r4] = m_new;
                sL[r4] = sL[r4] * alpha + sum;
                sAlpha[r4] = alpha;
            }
        }
        __syncthreads();

        // GEMM2: O = O*alpha + P @ V
        {
            float a[4];
#pragma unroll
            for (int i = 0; i < 4; i++) a[i] = sAlpha[ty * 4 + i];
#pragma unroll
            for (int i = 0; i < 4; i++)
#pragma unroll
                for (int j = 0; j < 4; j++) O[i * 4 + j] *= a[i];
#pragma unroll 8
            for (int c = 0; c < 64; c++) {
                float pr[4], vr[4];
#pragma unroll
                for (int i = 0; i < 4; i++) pr[i] = sP[(ty * 4 + i) * PAD + c];
#pragma unroll
                for (int j = 0; j < 4; j++) vr[j] = sKV[c * PAD + tx * 4 + j];
#pragma unroll
                for (int i = 0; i < 4; i++)
#pragma unroll
                    for (int j = 0; j < 4; j++) O[i * 4 + j] += pr[i] * vr[j];
            }
        }
        __syncthreads();
    }

    // Epilogue: normalize, write [b, t, h*64 + d]
#pragma unroll
    for (int i = 0; i < 4; i++) {
        float inv = 1.0f / sL[ty * 4 + i];
        int t = i0 + ty * 4 + i;
        float* dst = out + ((size_t)(b * Tc + t)) * Cc + h * 64 + tx * 4;
        float4 v;
        v.x = O[i * 4 + 0] * inv; v.y = O[i * 4 + 1] * inv;
        v.z = O[i * 4 + 2] * inv; v.w = O[i * 4 + 3] * inv;
        *(float4*)dst = v;
    }
}

// ---------------------------------------------------------------------------
extern "C" void kernel_launch(void* const* d_in, const int* in_sizes, int n_in,
                              void* d_out, int out_size)
{
    const float* x      = (const float*)d_in[0];
    const float* cosb   = (const float*)d_in[1];
    const float* sinb   = (const float*)d_in[2];
    const float* attn_w = (const float*)d_in[3];
    const float* attn_b = (const float*)d_in[4];
    const float* proj_w = (const float*)d_in[5];
    const float* proj_b = (const float*)d_in[6];
    float* out = (float*)d_out;

    // Host-side, non-enqueueing lookups (capture-safe), done before any launch.
    float *qkv = nullptr, *att = nullptr;
    cudaGetSymbolAddress((void**)&qkv, g_qkv);
    cudaGetSymbolAddress((void**)&att, g_att);

    const int attn_smem = (64 * 64 + 2 * 64 * PAD + 3 * 64) * (int)sizeof(float);
    cudaFuncSetAttribute(attn_kernel,
                         cudaFuncAttributeMaxDynamicSharedMemorySize, attn_smem);

    // 1. QKV GEMM + bias: [4096,2048] x [3072,2048]^T -> [4096,3072]
    {
        dim3 grid(QKVN / 128, (Bc * Tc) / 128);
        sgemm_bias_kernel<<<grid, 256>>>(x, attn_w, attn_b, qkv,
                                         Bc * Tc, QKVN, Cc);
    }

    // 2. RoPE in-place on q,k
    {
        int total = Bc * Tc * NGRP * 5 * 32;
        rope_kernel<<<total / 256, 256>>>(cosb, sinb);
    }

    // 3. Flash attention
    {
        dim3 grid(Tc / 64, NHEAD, Bc);
        attn_kernel<<<grid, 256, attn_smem>>>(qkv, att);
    }

    // 4. Output projection + bias: [4096,2048] x [2048,2048]^T -> [4096,2048]
    {
        dim3 grid(Cc / 128, (Bc * Tc) / 128);
        sgemm_bias_kernel<<<grid, 256>>>(att, proj_w, proj_b, out,
                                         Bc * Tc, Cc, Cc);
    }
}

// round 12
// speedup vs baseline: 1.4072x; 1.4072x over previous
#include <cuda_runtime.h>
#include <cuda_bf16.h>
#include <cstdint>

// Problem constants
#define Bc 2
#define Tc 2048
#define Cc 2048
#define NHEAD 32
#define NGRP 8
#define HS 64
#define QKVN 3072   // (32 + 2*8) * 64
#define MROWS (Bc * Tc)   // 4096

// Scratch (static device globals: no allocation in kernel_launch)
__device__ float g_qkv[(size_t)MROWS * QKVN];  // [b, t, g, r(0..5), d]

// bf16 hi/lo split buffers
__device__ __nv_bfloat16 g_xh[(size_t)MROWS * Cc];
__device__ __nv_bfloat16 g_xl[(size_t)MROWS * Cc];
__device__ __nv_bfloat16 g_wh[(size_t)QKVN * Cc];
__device__ __nv_bfloat16 g_wl[(size_t)QKVN * Cc];
__device__ __nv_bfloat16 g_ah[(size_t)MROWS * Cc];
__device__ __nv_bfloat16 g_al[(size_t)MROWS * Cc];
__device__ __nv_bfloat16 g_ph[(size_t)Cc * Cc];
__device__ __nv_bfloat16 g_pl[(size_t)Cc * Cc];

// ---------------------------------------------------------------------------
// Split fp32 -> (hi, lo) bf16.  hi = bf16(v), lo = bf16(v - hi).
// ---------------------------------------------------------------------------
__global__ __launch_bounds__(256) void split_kernel(
    const float* __restrict__ in, __nv_bfloat16* __restrict__ hi,
    __nv_bfloat16* __restrict__ lo, int n4)
{
    int i = blockIdx.x * 256 + threadIdx.x;
    if (i >= n4) return;
    float4 v = ((const float4*)in)[i];
    __nv_bfloat16 h0 = __float2bfloat16(v.x);
    __nv_bfloat16 h1 = __float2bfloat16(v.y);
    __nv_bfloat16 h2 = __float2bfloat16(v.z);
    __nv_bfloat16 h3 = __float2bfloat16(v.w);
    __nv_bfloat16 l0 = __float2bfloat16(v.x - __bfloat162float(h0));
    __nv_bfloat16 l1 = __float2bfloat16(v.y - __bfloat162float(h1));
    __nv_bfloat16 l2 = __float2bfloat16(v.z - __bfloat162float(h2));
    __nv_bfloat16 l3 = __float2bfloat16(v.w - __bfloat162float(h3));
    __nv_bfloat162 hh0 = __nv_bfloat162(h0, h1), hh1 = __nv_bfloat162(h2, h3);
    __nv_bfloat162 ll0 = __nv_bfloat162(l0, l1), ll1 = __nv_bfloat162(l2, l3);
    ((__nv_bfloat162*)hi)[i * 2]     = hh0;
    ((__nv_bfloat162*)hi)[i * 2 + 1] = hh1;
    ((__nv_bfloat162*)lo)[i * 2]     = ll0;
    ((__nv_bfloat162*)lo)[i * 2 + 1] = ll1;
}

// ---------------------------------------------------------------------------
// bf16 tensor-core GEMM with hi/lo compensation:
//   C[m][n] = sum_k (Ah Bh + Ah Bl + Al Bh)[m][n] + bias[n]
// A*: [M,K] row-major bf16, B*: [N,K] row-major bf16 (i.e. C = A @ B^T).
// 128x128 CTA tile, BK=32, 8 warps (4 in M x 2 in N), warp tile 32x64.
// mma.sync.m16n8k16 + ldmatrix, double-buffered smem, 80-byte padded rows.
// ---------------------------------------------------------------------------
#define SROW 40   // bf16 elements per smem row (80 bytes)

__device__ __forceinline__ void mma16816(
    float c[4], const uint32_t a[4], uint32_t b0, uint32_t b1)
{
    asm volatile(
        "mma.sync.aligned.m16n8k16.row.col.f32.bf16.bf16.f32 "
        "{%0,%1,%2,%3}, {%4,%5,%6,%7}, {%8,%9}, {%0,%1,%2,%3};"
        : "+f"(c[0]), "+f"(c[1]), "+f"(c[2]), "+f"(c[3])
        : "r"(a[0]), "r"(a[1]), "r"(a[2]), "r"(a[3]), "r"(b0), "r"(b1));
}

__device__ __forceinline__ void ldsm4(uint32_t r[4], uint32_t addr)
{
    asm volatile(
        "ldmatrix.sync.aligned.m8n8.x4.shared.b16 {%0,%1,%2,%3}, [%4];"
        : "=r"(r[0]), "=r"(r[1]), "=r"(r[2]), "=r"(r[3]) : "r"(addr));
}

__global__ __launch_bounds__(256) void gemm_bf16c_kernel(
    const __nv_bfloat16* __restrict__ Ah, const __nv_bfloat16* __restrict__ Al,
    const __nv_bfloat16* __restrict__ Bh, const __nv_bfloat16* __restrict__ Bl,
    const float* __restrict__ bias, float* __restrict__ C,
    int M, int N, int K)
{
    __shared__ __nv_bfloat16 sA[2][128][SROW];
    __shared__ __nv_bfloat16 sB[2][128][SROW];
    const uint32_t BUFSZ = 128 * SROW * 2;   // bytes per buffer

    const int tid  = threadIdx.x;
    const int wid  = tid >> 5;
    const int lane = tid & 31;
    const int mw   = wid >> 1;    // 0..3 (M)
    const int nw   = wid & 1;     // 0..1 (N)
    const int m0   = blockIdx.y * 128;
    const int n0   = blockIdx.x * 128;

    // loader: thread handles rows r0 and r0+64, 16B chunk kp (elements)
    const int r0  = tid >> 2;          // 0..63
    const int r1  = r0 + 64;
    const int kp  = (tid & 3) * 8;     // element offset of 16B chunk

    // ldmatrix lane base offsets (bytes within one buffer)
    uint32_t sA0 = (uint32_t)__cvta_generic_to_shared(&sA[0][0][0]);
    uint32_t sB0 = (uint32_t)__cvta_generic_to_shared(&sB[0][0][0]);
    const int rowA = mw * 32 + (lane & 7) + ((lane >> 3) & 1) * 8;
    const uint32_t aoff = sA0 + rowA * (SROW * 2) + (lane >> 4) * 16;
    const int rowB = nw * 64 + (lane & 7) + ((lane >> 4) & 1) * 8;
    const uint32_t boff = sB0 + rowB * (SROW * 2) + ((lane >> 3) & 1) * 16;

    float acc[2][8][4];
#pragma unroll
    for (int mi = 0; mi < 2; mi++)
#pragma unroll
        for (int ni = 0; ni < 8; ni++)
#pragma unroll
            for (int q = 0; q < 4; q++) acc[mi][ni][q] = 0.f;

    const __nv_bfloat16* pA[3] = { Ah, Ah, Al };
    const __nv_bfloat16* pB[3] = { Bh, Bl, Bh };

    auto compute = [&](int buf) {
#pragma unroll
        for (int kk = 0; kk < 2; kk++) {
            uint32_t a[2][4];
#pragma unroll
            for (int mi = 0; mi < 2; mi++)
                ldsm4(a[mi], aoff + buf * BUFSZ + mi * 16 * (SROW * 2) + kk * 32);
            uint32_t b[4][4];
#pragma unroll
            for (int np = 0; np < 4; np++)
                ldsm4(b[np], boff + buf * BUFSZ + np * 16 * (SROW * 2) + kk * 32);
#pragma unroll
            for (int mi = 0; mi < 2; mi++)
#pragma unroll
                for (int ni = 0; ni < 8; ni++)
                    mma16816(acc[mi][ni], a[mi],
                             b[ni >> 1][(ni & 1) * 2], b[ni >> 1][(ni & 1) * 2 + 1]);
        }
    };

    int buf = 0;
    for (int pass = 0; pass < 3; pass++) {
        const __nv_bfloat16* Ap = pA[pass];
        const __nv_bfloat16* Bp = pB[pass];
        __syncthreads();   // protect buf from overwrite while prior compute runs
        // Prologue: fill current buf directly
        {
            *(uint4*)&sA[buf][r0][kp] = *(const uint4*)(Ap + (size_t)(m0 + r0) * K + kp);
            *(uint4*)&sA[buf][r1][kp] = *(const uint4*)(Ap + (size_t)(m0 + r1) * K + kp);
            *(uint4*)&sB[buf][r0][kp] = *(const uint4*)(Bp + (size_t)(n0 + r0) * K + kp);
            *(uint4*)&sB[buf][r1][kp] = *(const uint4*)(Bp + (size_t)(n0 + r1) * K + kp);
        }
        __syncthreads();
        for (int k0 = 32; k0 < K; k0 += 32) {
            uint4 pa0 = *(const uint4*)(Ap + (size_t)(m0 + r0) * K + k0 + kp);
            uint4 pa1 = *(const uint4*)(Ap + (size_t)(m0 + r1) * K + k0 + kp);
            uint4 pb0 = *(const uint4*)(Bp + (size_t)(n0 + r0) * K + k0 + kp);
            uint4 pb1 = *(const uint4*)(Bp + (size_t)(n0 + r1) * K + k0 + kp);
            compute(buf);
            int nb = buf ^ 1;
            *(uint4*)&sA[nb][r0][kp] = pa0;
            *(uint4*)&sA[nb][r1][kp] = pa1;
            *(uint4*)&sB[nb][r0][kp] = pb0;
            *(uint4*)&sB[nb][r1][kp] = pb1;
            __syncthreads();
            buf = nb;
        }
        compute(buf);
    }

    // Epilogue: bias + fp32 store
    const int mrow = m0 + mw * 32;
    const int ncol = n0 + nw * 64;
#pragma unroll
    for (int mi = 0; mi < 2; mi++) {
        int r = mrow + mi * 16 + (lane >> 2);
#pragma unroll
        for (int ni = 0; ni < 8; ni++) {
            int c = ncol + ni * 8 + (lane & 3) * 2;
            float bv0 = bias[c], bv1 = bias[c + 1];
            float2 v0 = { acc[mi][ni][0] + bv0, acc[mi][ni][1] + bv1 };
            float2 v1 = { acc[mi][ni][2] + bv0, acc[mi][ni][3] + bv1 };
            *(float2*)(C + (size_t)r * N + c)       = v0;
            *(float2*)(C + (size_t)(r + 8) * N + c) = v1;
        }
    }
}

// ---------------------------------------------------------------------------
// RoPE in-place on q (r=0..3) and k (r=4) rows of g_qkv.
// ---------------------------------------------------------------------------
__global__ __launch_bounds__(256) void rope_kernel(const float* __restrict__ cosb,
                                                   const float* __restrict__ sinb)
{
    int idx = blockIdx.x * 256 + threadIdx.x;   // total = B*T*G*5*32
    int d    = idx & 31;
    int idx2 = idx >> 5;
    int r    = idx2 % 5;
    int idx3 = idx2 / 5;          // = b*16384 + t*8 + g
    int g    = idx3 & 7;
    int t    = (idx3 >> 3) & 2047;
    int b    = idx3 >> 14;

    float* base = g_qkv + (size_t)(b * Tc + t) * QKVN + g * 384 + r * 64;
    float c1 = cosb[t * 64 + d],      s1 = sinb[t * 64 + d];
    float c2 = cosb[t * 64 + 32 + d], s2 = sinb[t * 64 + 32 + d];
    float x1 = base[d], x2 = base[d + 32];
    base[d]      = x1 * c1 - x2 * s1;
    base[d + 32] = x2 * c2 + x1 * s2;
}

// ---------------------------------------------------------------------------
// Causal flash attention (fp32 math). Epilogue writes hi/lo bf16 split
// directly (feeds the projection GEMM), eliminating the fp32 att buffer
// and its separate split pass.
// ---------------------------------------------------------------------------
#define PAD 65

__global__ __launch_bounds__(256) void attn_kernel(
    const float* __restrict__ qkv,
    __nv_bfloat16* __restrict__ oh, __nv_bfloat16* __restrict__ ol)
{
    extern __shared__ float sm[];
    float* sQ     = sm;                 // [64][64]
    float* sKV    = sQ + 64 * 64;       // [64][PAD]
    float* sP     = sKV + 64 * PAD;     // [64][PAD]
    float* sM     = sP + 64 * PAD;      // [64]
    float* sL     = sM + 64;            // [64]
    float* sAlpha = sL + 64;            // [64]

    const int tid = threadIdx.x;
    const int i0 = blockIdx.x * 64;
    const int h  = blockIdx.y;
    const int b  = blockIdx.z;
    const int g  = h >> 2;
    const int qi = h & 3;
    const float scale = 0.125f;

    const float* qbase = qkv + (size_t)b * Tc * QKVN + g * 384 + qi * 64;
    const float* kbase = qkv + (size_t)b * Tc * QKVN + g * 384 + 4 * 64;
    const float* vbase = qkv + (size_t)b * Tc * QKVN + g * 384 + 5 * 64;

    const int llr = tid >> 4;
    const int llc = (tid & 15) * 4;

#pragma unroll
    for (int u = 0; u < 4; u++) {
        int row = llr + u * 16;
        float4 v = *(const float4*)(qbase + (size_t)(i0 + row) * QKVN + llc);
        float* dst = sQ + row * 64 + llc;
        dst[0] = v.x * scale; dst[1] = v.y * scale;
        dst[2] = v.z * scale; dst[3] = v.w * scale;
    }
    if (tid < 64) { sM[tid] = -1e30f; sL[tid] = 0.f; }

    const int tx = tid & 15, ty = tid >> 4;
    const int r4  = tid >> 2;
    const int c16 = (tid & 3) * 16;

    float O[16];
#pragma unroll
    for (int i = 0; i < 16; i++) O[i] = 0.f;

    __syncthreads();

    const int ntiles = (i0 >> 6) + 1;
    for (int jt = 0; jt < ntiles; jt++) {
        const int j0 = jt * 64;

#pragma unroll
        for (int u = 0; u < 4; u++) {
            int row = llr + u * 16;
            float4 v = *(const float4*)(kbase + (size_t)(j0 + row) * QKVN + llc);
            float* dst = sKV + row * PAD + llc;
            dst[0] = v.x; dst[1] = v.y; dst[2] = v.z; dst[3] = v.w;
        }
        __syncthreads();

        {
            float s[4][4];
#pragma unroll
            for (int i = 0; i < 4; i++)
#pragma unroll
                for (int j = 0; j < 4; j++) s[i][j] = 0.f;
#pragma unroll 8
            for (int d = 0; d < 64; d++) {
                float qa[4], kb[4];
#pragma unroll
                for (int i = 0; i < 4; i++) qa[i] = sQ[(ty * 4 + i) * 64 + d];
#pragma unroll
                for (int j = 0; j < 4; j++) kb[j] = sKV[(tx * 4 + j) * PAD + d];
#pragma unroll
                for (int i = 0; i < 4; i++)
#pragma unroll
                    for (int j = 0; j < 4; j++) s[i][j] += qa[i] * kb[j];
            }
#pragma unroll
            for (int i = 0; i < 4; i++)
#pragma unroll
                for (int j = 0; j < 4; j++) {
                    int grow = i0 + ty * 4 + i;
                    int gcol = j0 + tx * 4 + j;
                    sP[(ty * 4 + i) * PAD + tx * 4 + j] =
                        (gcol <= grow) ? s[i][j] : -1e30f;
                }
        }
        __syncthreads();

#pragma unroll
        for (int u = 0; u < 4; u++) {
            int row = llr + u * 16;
            float4 v = *(const float4*)(vbase + (size_t)(j0 + row) * QKVN + llc);
            float* dst = sKV + row * PAD + llc;
            dst[0] = v.x; dst[1] = v.y; dst[2] = v.z; dst[3] = v.w;
        }
        {
            float p[16];
            float m_tile = -1e30f;
#pragma unroll
            for (int k = 0; k < 16; k++) {
                p[k] = sP[r4 * PAD + c16 + k];
                m_tile = fmaxf(m_tile, p[k]);
            }
            m_tile = fmaxf(m_tile, __shfl_xor_sync(0xffffffffu, m_tile, 1));
            m_tile = fmaxf(m_tile, __shfl_xor_sync(0xffffffffu, m_tile, 2));
            float m_old = sM[r4];
            float m_new = fmaxf(m_old, m_tile);
            float alpha = __expf(m_old - m_new);
            float sum = 0.f;
#pragma unroll
            for (int k = 0; k < 16; k++) {
                p[k] = __expf(p[k] - m_new);
                sum += p[k];
            }
            sum += __shfl_xor_sync(0xffffffffu, sum, 1);
            sum += __shfl_xor_sync(0xffffffffu, sum, 2);
#pragma unroll
            for (int k = 0; k < 16; k++) sP[r4 * PAD + c16 + k] = p[k];
            if ((tid & 3) == 0) {
                sM[r4] = m_new;
                sL[r4] = sL[r4] * alpha + sum;
                sAlpha[r4] = alpha;
            }
        }
        __syncthreads();

        {
            float a[4];
#pragma unroll
            for (int i = 0; i < 4; i++) a[i] = sAlpha[ty * 4 + i];
#pragma unroll
            for (int i = 0; i < 4; i++)
#pragma unroll
                for (int j = 0; j < 4; j++) O[i * 4 + j] *= a[i];
#pragma unroll 8
            for (int c = 0; c < 64; c++) {
                float pr[4], vr[4];
#pragma unroll
                for (int i = 0; i < 4; i++) pr[i] = sP[(ty * 4 + i) * PAD + c];
#pragma unroll
                for (int j = 0; j < 4; j++) vr[j] = sKV[c * PAD + tx * 4 + j];
#pragma unroll
                for (int i = 0; i < 4; i++)
#pragma unroll
                    for (int j = 0; j < 4; j++) O[i * 4 + j] += pr[i] * vr[j];
            }
        }
        __syncthreads();
    }

    // Epilogue: normalize, split to hi/lo bf16, write [b, t, h*64 + d]
#pragma unroll
    for (int i = 0; i < 4; i++) {
        float inv = 1.0f / sL[ty * 4 + i];
        int t = i0 + ty * 4 + i;
        size_t idx = ((size_t)(b * Tc + t)) * Cc + h * 64 + tx * 4;
        __nv_bfloat16 hh[4], ll[4];
#pragma unroll
        for (int j = 0; j < 4; j++) {
            float v = O[i * 4 + j] * inv;
            hh[j] = __float2bfloat16(v);
            ll[j] = __float2bfloat16(v - __bfloat162float(hh[j]));
        }
        *(uint2*)(oh + idx) = *(uint2*)hh;
        *(uint2*)(ol + idx) = *(uint2*)ll;
    }
}

// ---------------------------------------------------------------------------
extern "C" void kernel_launch(void* const* d_in, const int* in_sizes, int n_in,
                              void* d_out, int out_size)
{
    const float* x      = (const float*)d_in[0];
    const float* cosb   = (const float*)d_in[1];
    const float* sinb   = (const float*)d_in[2];
    const float* attn_w = (const float*)d_in[3];
    const float* attn_b = (const float*)d_in[4];
    const float* proj_w = (const float*)d_in[5];
    const float* proj_b = (const float*)d_in[6];
    float* out = (float*)d_out;

    float *qkv = nullptr;
    __nv_bfloat16 *xh, *xl, *wh, *wl, *ah, *al, *ph, *pl;
    cudaGetSymbolAddress((void**)&qkv, g_qkv);
    cudaGetSymbolAddress((void**)&xh, g_xh);
    cudaGetSymbolAddress((void**)&xl, g_xl);
    cudaGetSymbolAddress((void**)&wh, g_wh);
    cudaGetSymbolAddress((void**)&wl, g_wl);
    cudaGetSymbolAddress((void**)&ah, g_ah);
    cudaGetSymbolAddress((void**)&al, g_al);
    cudaGetSymbolAddress((void**)&ph, g_ph);
    cudaGetSymbolAddress((void**)&pl, g_pl);

    const int attn_smem = (64 * 64 + 2 * 64 * PAD + 3 * 64) * (int)sizeof(float);
    cudaFuncSetAttribute(attn_kernel,
                         cudaFuncAttributeMaxDynamicSharedMemorySize, attn_smem);

    // 0. Split inputs to bf16 hi/lo
    {
        int n4 = (MROWS * Cc) / 4;
        split_kernel<<<(n4 + 255) / 256, 256>>>(x, xh, xl, n4);
        n4 = (QKVN * Cc) / 4;
        split_kernel<<<(n4 + 255) / 256, 256>>>(attn_w, wh, wl, n4);
        n4 = (Cc * Cc) / 4;
        split_kernel<<<(n4 + 255) / 256, 256>>>(proj_w, ph, pl, n4);
    }

    // 1. QKV GEMM (tensor cores, compensated): [4096,2048] x [3072,2048]^T
    {
        dim3 grid(QKVN / 128, MROWS / 128);
        gemm_bf16c_kernel<<<grid, 256>>>(xh, xl, wh, wl, attn_b, qkv,
                                         MROWS, QKVN, Cc);
    }

    // 2. RoPE in-place on q,k
    {
        int total = Bc * Tc * NGRP * 5 * 32;
        rope_kernel<<<total / 256, 256>>>(cosb, sinb);
    }

    // 3. Flash attention (fp32 math, bf16 hi/lo output)
    {
        dim3 grid(Tc / 64, NHEAD, Bc);
        attn_kernel<<<grid, 256, attn_smem>>>(qkv, ah, al);
    }

    // 4. Projection GEMM (tensor cores, compensated)
    {
        dim3 grid(Cc / 128, MROWS / 128);
        gemm_bf16c_kernel<<<grid, 256>>>(ah, al, ph, pl, proj_b, out,
                                         MROWS, Cc, Cc);
    }
}